// round 9
// baseline (speedup 1.0000x reference)
#include <cuda_runtime.h>
#include <math.h>

#define NM      4096
#define NPTS    131072
#define GRES    16

typedef unsigned long long u64;

// ---- scratch (no allocations allowed) ----
__device__ int g_cnt[NM];      // zero at load; re-zeroed by k_mlp each call
__device__ int g_off[NM];
__device__ int g_start[NM];
__device__ int g_vox[NPTS];
__device__ int g_sorted[NPTS];

__global__ void k_index(const float* __restrict__ pts) {
    int n = blockIdx.x * blockDim.x + threadIdx.x;
    if (n >= NPTS) return;
    float x = pts[3 * n + 0], y = pts[3 * n + 1], z = pts[3 * n + 2];
    int ix = (int)fminf(fmaxf(x * (float)GRES, 0.f), (float)(GRES - 1));
    int iy = (int)fminf(fmaxf(y * (float)GRES, 0.f), (float)(GRES - 1));
    int iz = (int)fminf(fmaxf(z * (float)GRES, 0.f), (float)(GRES - 1));
    int v = ix * (GRES * GRES) + iy * GRES + iz;
    g_vox[n] = v;
    atomicAdd(&g_cnt[v], 1);
}

__global__ void k_scan() {
    __shared__ int sh[1024];
    int t = threadIdx.x;
    int c0 = g_cnt[4 * t + 0], c1 = g_cnt[4 * t + 1];
    int c2 = g_cnt[4 * t + 2], c3 = g_cnt[4 * t + 3];
    int s = c0 + c1 + c2 + c3;
    sh[t] = s;
    __syncthreads();
    for (int d = 1; d < 1024; d <<= 1) {
        int v = (t >= d) ? sh[t - d] : 0;
        __syncthreads();
        sh[t] += v;
        __syncthreads();
    }
    int excl = sh[t] - s;
    g_start[4 * t + 0] = excl; g_off[4 * t + 0] = excl; excl += c0;
    g_start[4 * t + 1] = excl; g_off[4 * t + 1] = excl; excl += c1;
    g_start[4 * t + 2] = excl; g_off[4 * t + 2] = excl; excl += c2;
    g_start[4 * t + 3] = excl; g_off[4 * t + 3] = excl;
}

__global__ void k_scatter() {
    int n = blockIdx.x * blockDim.x + threadIdx.x;
    if (n >= NPTS) return;
    int v = g_vox[n];
    int pos = atomicAdd(&g_off[v], 1);
    g_sorted[pos] = n;
}

// ---- packed fp32x2 helpers ----
__device__ __forceinline__ u64 f2fma(u64 a, u64 b, u64 c) {
    u64 d;
    asm("fma.rn.f32x2 %0, %1, %2, %3;" : "=l"(d) : "l"(a), "l"(b), "l"(c));
    return d;
}
__device__ __forceinline__ u64 pk2(float v) {
    u64 r;
    asm("mov.b64 %0, {%1, %1};" : "=l"(r) : "f"(v));
    return r;
}
__device__ __forceinline__ float2 unpk(u64 p) {
    float2 f;
    asm("mov.b64 {%0, %1}, %2;" : "=f"(f.x), "=f"(f.y) : "l"(p));
    return f;
}
// dual-point: one weight load feeds both points' accumulators
__device__ __forceinline__ void accP2(u64* P0, u64* P1, const float* wrow,
                                      u64 v0, u64 v1) {
    const ulonglong2* w = reinterpret_cast<const ulonglong2*>(wrow);
#pragma unroll
    for (int j = 0; j < 8; j++) {
        ulonglong2 ww = w[j];
        P0[2 * j + 0] = f2fma(v0, ww.x, P0[2 * j + 0]);
        P0[2 * j + 1] = f2fma(v0, ww.y, P0[2 * j + 1]);
        P1[2 * j + 0] = f2fma(v1, ww.x, P1[2 * j + 0]);
        P1[2 * j + 1] = f2fma(v1, ww.y, P1[2 * j + 1]);
    }
}
__device__ __forceinline__ void loadP(u64* P, const float* s) {
    const ulonglong2* b = reinterpret_cast<const ulonglong2*>(s);
#pragma unroll
    for (int j = 0; j < 8; j++) {
        ulonglong2 v = b[j];
        P[2 * j + 0] = v.x;
        P[2 * j + 1] = v.y;
    }
}
__device__ __forceinline__ void unpackRelu(const u64* P, float* H) {
#pragma unroll
    for (int j = 0; j < 16; j++) {
        float2 f = unpk(P[j]);
        H[2 * j + 0] = fmaxf(f.x, 0.f);
        H[2 * j + 1] = fmaxf(f.y, 0.f);
    }
}
__device__ __forceinline__ void unpackPlain(const u64* P, float* H) {
#pragma unroll
    for (int j = 0; j < 16; j++) {
        float2 f = unpk(P[j]);
        H[2 * j + 0] = f.x;
        H[2 * j + 1] = f.y;
    }
}

// ---- staging (32 threads, __syncwarp): (32 x C) row-major -> T[d*32+o] ----
// 16-row halves through scratch (needs >= 16*C floats)
__device__ __forceinline__ void stage16(const float* g, float* T, float* scr,
                                        int tid, int C) {
    for (int h = 0; h < 2; h++) {
        const float4* g4 = reinterpret_cast<const float4*>(g + h * 16 * C);
        float4* s4 = reinterpret_cast<float4*>(scr);
        int n4 = (16 * C) >> 2;
        for (int i = tid; i < n4; i += 32) s4[i] = g4[i];
        __syncwarp();
        for (int i = tid; i < 16 * C; i += 32) {
            int d = i >> 4, o = i & 15;
            T[d * 32 + h * 16 + o] = scr[o * C + d];
        }
        __syncwarp();
    }
}
// 32x32 via padded (33) scratch, 16-row halves (needs >= 528 floats)
__device__ __forceinline__ void stage32p(const float* g, float* T, float* scr,
                                         int tid) {
    for (int h = 0; h < 2; h++) {
        const float* gh = g + h * 512;
        for (int i = tid; i < 512; i += 32)
            scr[(i >> 5) * 33 + (i & 31)] = gh[i];
        __syncwarp();
        for (int i = tid; i < 512; i += 32) {
            int d = i >> 4, o = i & 15;
            T[d * 32 + h * 16 + o] = scr[o * 33 + d];
        }
        __syncwarp();
    }
}
// 32x32 via small padded scratch, 8-row chunks (needs >= 264 floats)
__device__ __forceinline__ void stage32s(const float* g, float* T, float* scr,
                                         int tid) {
#pragma unroll
    for (int h = 0; h < 4; h++) {
        const float* gh = g + h * 256;
        for (int i = tid; i < 256; i += 32)
            scr[(i >> 5) * 33 + (i & 31)] = gh[i];
        __syncwarp();
        for (int i = tid; i < 256; i += 32) {
            int d = i >> 3, o = i & 7;
            T[d * 32 + h * 8 + o] = scr[o * 33 + d];
        }
        __syncwarp();
    }
}

// smem pool layout (floats)
#define OFF_W0T 0        // 2016
#define OFF_W1T 2016     // 1024
#define OFF_FT  3040     // 1024
#define OFF_VT  4064     // 1888
#define OFF_SM  5952     // 264
#define SP_TOT  6216     // 24864 bytes -> 8 blocks/SM comfortably

__global__ void __launch_bounds__(32, 8) k_mlp(
    const float* __restrict__ pts, const float* __restrict__ vdirs,
    const float* __restrict__ w0, const float* __restrict__ b0,
    const float* __restrict__ w1, const float* __restrict__ b1,
    const float* __restrict__ fw, const float* __restrict__ fb,
    const float* __restrict__ sw, const float* __restrict__ sb,
    const float* __restrict__ vw, const float* __restrict__ vb,
    const float* __restrict__ rw, const float* __restrict__ rb,
    float* __restrict__ out)
{
    const int vox = blockIdx.x;
    const int lane = threadIdx.x;

    __shared__ __align__(16) float sp[SP_TOT];
    float* s_w0T = sp + OFF_W0T;   // [d=63][o=32]
    float* s_w1T = sp + OFF_W1T;   // [d=32][o=32]
    float* s_fT  = sp + OFF_FT;    // [d=32][o=32]
    float* s_vT  = sp + OFF_VT;    // [d=59][o=32]
    float* s_sm  = sp + OFF_SM;

    const int start = g_start[vox];
    const int count = g_cnt[vox];

    // staging order: w0T/vT/fT use the (empty) w1T region as scratch;
    // w1T last uses the (empty) s_sm region as scratch
    stage16(w0 + (size_t)vox * 2016, s_w0T, s_w1T, lane, 63);
    stage16(vw + (size_t)vox * 1888, s_vT, s_w1T, lane, 59);
    stage32p(fw + (size_t)vox * 1024, s_fT, s_w1T, lane);
    stage32s(w1 + (size_t)vox * 1024, s_w1T, s_sm, lane);

    // small region: sw[0..31], b0[32..63], b1[64..95], fb[96..127],
    // vb[128..159], rT[160..255], rb[256..258], sb[259]
    {
        int c0 = lane >> 5, d0 = lane & 31;  // lane<32: c0=0
        s_sm[160 + d0 * 3 + c0] = rw[(size_t)vox * 96 + lane];
        s_sm[160 + (d0) * 3 + 1] = rw[(size_t)vox * 96 + 32 + lane];
        s_sm[160 + (d0) * 3 + 2] = rw[(size_t)vox * 96 + 64 + lane];
        s_sm[lane]       = sw[(size_t)vox * 32 + lane];
        s_sm[32 + lane]  = b0[(size_t)vox * 32 + lane];
        s_sm[64 + lane]  = b1[(size_t)vox * 32 + lane];
        s_sm[96 + lane]  = fb[(size_t)vox * 32 + lane];
        s_sm[128 + lane] = vb[(size_t)vox * 32 + lane];
    }
    if (lane < 3) s_sm[256 + lane] = rb[(size_t)vox * 3 + lane];
    if (lane == 0) {
        s_sm[259] = sb[vox];
        g_cnt[vox] = 0;   // reset for next replay (count already read above)
    }
    __syncwarp();

    // dual-point pairs: (j, j+half) so one weight load feeds two points
    const int half = (count + 1) >> 1;

    for (int pb = 0; pb < half; pb += 32) {
        const int j = pb + lane;
        const bool a0 = (j < half);
        const bool a1 = (j + half < count);
        int n0 = 0, n1 = 0;
        float px0 = 0.f, py0 = 0.f, pz0 = 0.f, dx0 = 0.f, dy0 = 0.f, dz0 = 0.f;
        float px1 = 0.f, py1 = 0.f, pz1 = 0.f, dx1 = 0.f, dy1 = 0.f, dz1 = 0.f;
        if (a0) {
            n0 = g_sorted[start + j];
            px0 = pts[3 * n0 + 0]; py0 = pts[3 * n0 + 1]; pz0 = pts[3 * n0 + 2];
            int r = n0 >> 7;
            dx0 = vdirs[3 * r + 0]; dy0 = vdirs[3 * r + 1]; dz0 = vdirs[3 * r + 2];
        }
        if (a1) {
            n1 = g_sorted[start + j + half];
            px1 = pts[3 * n1 + 0]; py1 = pts[3 * n1 + 1]; pz1 = pts[3 * n1 + 2];
            int r = n1 >> 7;
            dx1 = vdirs[3 * r + 0]; dy1 = vdirs[3 * r + 1]; dz1 = vdirs[3 * r + 2];
        }

        u64 P0[16], P1[16];
        float A0[32], A1[32];   // single activation pair, reused across layers

        // ---- layer0: 63 -> 32, relu ----
        loadP(P0, s_sm + 32);
        loadP(P1, s_sm + 32);
        accP2(P0, P1, s_w0T + 0 * 32, pk2(px0), pk2(px1));
        accP2(P0, P1, s_w0T + 1 * 32, pk2(py0), pk2(py1));
        accP2(P0, P1, s_w0T + 2 * 32, pk2(pz0), pk2(pz1));
        {
            float sx0 = __sinf(px0), cx0 = __cosf(px0);
            float sy0 = __sinf(py0), cy0 = __cosf(py0);
            float sz0 = __sinf(pz0), cz0 = __cosf(pz0);
            float sx1 = __sinf(px1), cx1 = __cosf(px1);
            float sy1 = __sinf(py1), cy1 = __cosf(py1);
            float sz1 = __sinf(pz1), cz1 = __cosf(pz1);
#pragma unroll
            for (int k = 0; k < 10; k++) {
                const float* r = s_w0T + (3 + 6 * k) * 32;
                accP2(P0, P1, r + 0 * 32, pk2(sx0), pk2(sx1));
                accP2(P0, P1, r + 1 * 32, pk2(sy0), pk2(sy1));
                accP2(P0, P1, r + 2 * 32, pk2(sz0), pk2(sz1));
                accP2(P0, P1, r + 3 * 32, pk2(cx0), pk2(cx1));
                accP2(P0, P1, r + 4 * 32, pk2(cy0), pk2(cy1));
                accP2(P0, P1, r + 5 * 32, pk2(cz0), pk2(cz1));
                float t;
                t = 2.f * sx0 * cx0; cx0 = 1.f - 2.f * sx0 * sx0; sx0 = t;
                t = 2.f * sy0 * cy0; cy0 = 1.f - 2.f * sy0 * sy0; sy0 = t;
                t = 2.f * sz0 * cz0; cz0 = 1.f - 2.f * sz0 * sz0; sz0 = t;
                t = 2.f * sx1 * cx1; cx1 = 1.f - 2.f * sx1 * sx1; sx1 = t;
                t = 2.f * sy1 * cy1; cy1 = 1.f - 2.f * sy1 * sy1; sy1 = t;
                t = 2.f * sz1 * cz1; cz1 = 1.f - 2.f * sz1 * sz1; sz1 = t;
            }
        }
        unpackRelu(P0, A0);
        unpackRelu(P1, A1);

        // ---- layer1: 32 -> 32, relu ----
        loadP(P0, s_sm + 64);
        loadP(P1, s_sm + 64);
#pragma unroll
        for (int d = 0; d < 32; d++)
            accP2(P0, P1, s_w1T + d * 32, pk2(A0[d]), pk2(A1[d]));
        unpackRelu(P0, A0);   // A now holds layer1 output (h)
        unpackRelu(P1, A1);

        // ---- sigma: 32 -> 1 ----
        float sg0 = s_sm[259], sg1 = sg0;
#pragma unroll
        for (int d = 0; d < 32; d++) {
            float w = s_sm[d];
            sg0 = fmaf(A0[d], w, sg0);
            sg1 = fmaf(A1[d], w, sg1);
        }

        // ---- feat: 32 -> 32 (no relu) ----
        loadP(P0, s_sm + 96);
        loadP(P1, s_sm + 96);
#pragma unroll
        for (int d = 0; d < 32; d++)
            accP2(P0, P1, s_fT + d * 32, pk2(A0[d]), pk2(A1[d]));
        unpackPlain(P0, A0);  // A now holds feat
        unpackPlain(P1, A1);

        // ---- view: concat(feat[32], ev[27]) -> 32, relu ----
        loadP(P0, s_sm + 128);
        loadP(P1, s_sm + 128);
#pragma unroll
        for (int d = 0; d < 32; d++)
            accP2(P0, P1, s_vT + d * 32, pk2(A0[d]), pk2(A1[d]));
        accP2(P0, P1, s_vT + 32 * 32, pk2(dx0), pk2(dx1));
        accP2(P0, P1, s_vT + 33 * 32, pk2(dy0), pk2(dy1));
        accP2(P0, P1, s_vT + 34 * 32, pk2(dz0), pk2(dz1));
        {
            float sx0 = __sinf(dx0), cx0 = __cosf(dx0);
            float sy0 = __sinf(dy0), cy0 = __cosf(dy0);
            float sz0 = __sinf(dz0), cz0 = __cosf(dz0);
            float sx1 = __sinf(dx1), cx1 = __cosf(dx1);
            float sy1 = __sinf(dy1), cy1 = __cosf(dy1);
            float sz1 = __sinf(dz1), cz1 = __cosf(dz1);
#pragma unroll
            for (int k = 0; k < 4; k++) {
                const float* r = s_vT + (35 + 6 * k) * 32;
                accP2(P0, P1, r + 0 * 32, pk2(sx0), pk2(sx1));
                accP2(P0, P1, r + 1 * 32, pk2(sy0), pk2(sy1));
                accP2(P0, P1, r + 2 * 32, pk2(sz0), pk2(sz1));
                accP2(P0, P1, r + 3 * 32, pk2(cx0), pk2(cx1));
                accP2(P0, P1, r + 4 * 32, pk2(cy0), pk2(cy1));
                accP2(P0, P1, r + 5 * 32, pk2(cz0), pk2(cz1));
                float t;
                t = 2.f * sx0 * cx0; cx0 = 1.f - 2.f * sx0 * sx0; sx0 = t;
                t = 2.f * sy0 * cy0; cy0 = 1.f - 2.f * sy0 * sy0; sy0 = t;
                t = 2.f * sz0 * cz0; cz0 = 1.f - 2.f * sz0 * sz0; sz0 = t;
                t = 2.f * sx1 * cx1; cx1 = 1.f - 2.f * sx1 * sx1; sx1 = t;
                t = 2.f * sy1 * cy1; cy1 = 1.f - 2.f * sy1 * sy1; sy1 = t;
                t = 2.f * sz1 * cz1; cz1 = 1.f - 2.f * sz1 * sz1; sz1 = t;
            }
        }
        unpackRelu(P0, A0);   // A now holds view output
        unpackRelu(P1, A1);

        // ---- rgb: 32 -> 3 ----
        float r00 = s_sm[256], r01 = s_sm[257], r02 = s_sm[258];
        float r10 = r00, r11 = r01, r12 = r02;
#pragma unroll
        for (int d = 0; d < 32; d++) {
            float wv0 = s_sm[160 + d * 3 + 0];
            float wv1 = s_sm[160 + d * 3 + 1];
            float wv2 = s_sm[160 + d * 3 + 2];
            r00 = fmaf(A0[d], wv0, r00);
            r01 = fmaf(A0[d], wv1, r01);
            r02 = fmaf(A0[d], wv2, r02);
            r10 = fmaf(A1[d], wv0, r10);
            r11 = fmaf(A1[d], wv1, r11);
            r12 = fmaf(A1[d], wv2, r12);
        }

        if (a0) {
            out[3 * n0 + 0] = r00;
            out[3 * n0 + 1] = r01;
            out[3 * n0 + 2] = r02;
            out[(size_t)NPTS * 3 + n0] = sg0;
        }
        if (a1) {
            out[3 * n1 + 0] = r10;
            out[3 * n1 + 1] = r11;
            out[3 * n1 + 2] = r12;
            out[(size_t)NPTS * 3 + n1] = sg1;
        }
    }
}

extern "C" void kernel_launch(void* const* d_in, const int* in_sizes, int n_in,
                              void* d_out, int out_size) {
    (void)in_sizes; (void)n_in; (void)out_size;
    const float* pts = (const float*)d_in[0];
    const float* vd  = (const float*)d_in[1];
    const float* w0  = (const float*)d_in[2];
    const float* b0  = (const float*)d_in[3];
    const float* w1  = (const float*)d_in[4];
    const float* b1  = (const float*)d_in[5];
    const float* fw  = (const float*)d_in[6];
    const float* fb  = (const float*)d_in[7];
    const float* sw  = (const float*)d_in[8];
    const float* sb  = (const float*)d_in[9];
    const float* vw  = (const float*)d_in[10];
    const float* vb  = (const float*)d_in[11];
    const float* rw  = (const float*)d_in[12];
    const float* rb  = (const float*)d_in[13];

    k_index<<<512, 256>>>(pts);
    k_scan<<<1, 1024>>>();
    k_scatter<<<512, 256>>>();
    k_mlp<<<NM, 32>>>(pts, vd, w0, b0, w1, b1, fw, fb, sw, sb, vw, vb, rw, rb,
                      (float*)d_out);
}